// round 14
// baseline (speedup 1.0000x reference)
#include <cuda_runtime.h>
#include <math.h>
#include <cstdint>

// ---------------------------------------------------------------------------
// SparseExpertRouter: B=4,S=2048,D=1024,E=8,H=512,K=2 (+shared expert)
// Round 14: R13 + volatile-pinned raw A loads in modes 2/3. A is already
// tf32-rounded there; asm volatile ld.shared pins schedule so ptxas cannot
// hoist (R11/R12: hoisting -> 132 regs -> occ 1). Removes 16 of 24 cvts per
// s-step while keeping <=128 regs / 2 CTAs/SM.
// ---------------------------------------------------------------------------

namespace cfg {
constexpr int TOK = 8192;
constexpr int D   = 1024;
constexpr int E   = 8;
constexpr int H   = 512;
constexpr int BM  = 128, BN = 128, BK = 32;
constexpr int STAGES   = 2;
constexpr int A_STRIDE = BK + 4;                 // floats
constexpr int B_STRIDE = BN + 4;                 // floats
constexpr int A_BYTES  = BM * A_STRIDE * 4;      // 18432
constexpr int B_BYTES  = BK * B_STRIDE * 4;      // 16896
constexpr int STAGE_BYTES = A_BYTES + B_BYTES;   // 35328
constexpr int STAGE_OFF   = 1536;
constexpr int SMEM_BYTES  = STAGE_OFF + STAGES * STAGE_BYTES;  // 72192
}

// ---- device scratch (identical set to R13) ----
__device__ __align__(16) float g_Hexp[(size_t)cfg::E * cfg::TOK * cfg::H];
__device__ __align__(16) float g_Hs  [cfg::TOK * cfg::H];
__device__ __align__(16) float g_Y   [2 * cfg::TOK * cfg::D];
__device__ int   g_tok [cfg::E * cfg::TOK];
__device__ int   g_slot[cfg::E * cfg::TOK];
__device__ float g_wt  [cfg::E * cfg::TOK];
__device__ int   g_cnt [cfg::E];

// ---- helpers ----
__device__ __forceinline__ void cp16(uint32_t dst, const void* src, int sz) {
    asm volatile("cp.async.cg.shared.global [%0], [%1], 16, %2;\n"
                 :: "r"(dst), "l"(src), "r"(sz));
}
#define CP_COMMIT() asm volatile("cp.async.commit_group;\n" ::: "memory")
#define CP_WAIT1()  asm volatile("cp.async.wait_group 1;\n" ::: "memory")

__device__ __forceinline__ uint32_t smem_u32(const void* p) {
    uint32_t a;
    asm("{ .reg .u64 t; cvta.to.shared.u64 t, %1; cvt.u32.u64 %0, t; }"
        : "=r"(a) : "l"(p));
    return a;
}
__device__ __forceinline__ uint32_t f2tf(float f) {
    uint32_t u;
    asm("cvt.rna.tf32.f32 %0, %1;" : "=r"(u) : "f"(f));
    return u;
}
// Volatile smem load: ptxas cannot reorder across other volatile asm, pinning
// fragment live ranges to one i-iteration.
__device__ __forceinline__ uint32_t lds32v(uint32_t addr) {
    uint32_t v;
    asm volatile("ld.shared.b32 %0, [%1];" : "=r"(v) : "r"(addr));
    return v;
}
__device__ __forceinline__ void mma_tf32(float* c, const uint32_t* a,
                                         const uint32_t* b) {
    asm volatile(
        "mma.sync.aligned.m16n8k8.row.col.f32.tf32.tf32.f32 "
        "{%0,%1,%2,%3},{%4,%5,%6,%7},{%8,%9},{%0,%1,%2,%3};"
        : "+f"(c[0]), "+f"(c[1]), "+f"(c[2]), "+f"(c[3])
        : "r"(a[0]), "r"(a[1]), "r"(a[2]), "r"(a[3]), "r"(b[0]), "r"(b[1]));
}
__device__ __forceinline__ float gelu_exact(float v) {
    return 0.5f * v * (1.0f + erff(v * 0.7071067811865476f));
}

// ---------------------------------------------------------------------------
__global__ void zero_cnt_kernel() {
    if (threadIdx.x < cfg::E) g_cnt[threadIdx.x] = 0;
}

// One warp per token: gate scores, sigmoid*scale, top-2, normalize, lists.
__global__ void gate_kernel(const float* __restrict__ x,
                            const float* __restrict__ gW,
                            const float* __restrict__ route_scale) {
    using namespace cfg;
    int warp = (blockIdx.x * blockDim.x + threadIdx.x) >> 5;
    int lane = threadIdx.x & 31;
    if (warp >= TOK) return;
    const float* xr = x + (size_t)warp * D;

    float acc[E] = {0.f, 0.f, 0.f, 0.f, 0.f, 0.f, 0.f, 0.f};
    for (int d = lane; d < D; d += 32) {
        float xv = xr[d];
        const float4* g4 = reinterpret_cast<const float4*>(gW + (size_t)d * E);
        float4 a = g4[0], b = g4[1];
        acc[0] += xv * a.x; acc[1] += xv * a.y; acc[2] += xv * a.z; acc[3] += xv * a.w;
        acc[4] += xv * b.x; acc[5] += xv * b.y; acc[6] += xv * b.z; acc[7] += xv * b.w;
    }
#pragma unroll
    for (int e = 0; e < E; e++)
#pragma unroll
        for (int o = 16; o > 0; o >>= 1)
            acc[e] += __shfl_down_sync(0xffffffffu, acc[e], o);

    if (lane == 0) {
        float scale = route_scale[0];
        float s[E];
#pragma unroll
        for (int e = 0; e < E; e++) s[e] = scale / (1.0f + expf(-acc[e]));
        int i0 = 0;
#pragma unroll
        for (int e = 1; e < E; e++) if (s[e] > s[i0]) i0 = e;
        int i1 = -1;
#pragma unroll
        for (int e = 0; e < E; e++) {
            if (e == i0) continue;
            if (i1 < 0 || s[e] > s[i1]) i1 = e;
        }
        float inv = 1.0f / (s[i0] + s[i1]);
        int p0 = atomicAdd(&g_cnt[i0], 1);
        g_tok [i0 * TOK + p0] = warp;
        g_slot[i0 * TOK + p0] = warp * 2 + 0;
        g_wt  [i0 * TOK + p0] = s[i0] * inv;
        int p1 = atomicAdd(&g_cnt[i1], 1);
        g_tok [i1 * TOK + p1] = warp;
        g_slot[i1 * TOK + p1] = warp * 2 + 1;
        g_wt  [i1 * TOK + p1] = s[i1] * inv;
    }
}

// ---------------------------------------------------------------------------
// tf32 mma.sync grouped GEMM, 128x128 tile, 8 warps (2m x 4n), 4x4 m16n8k8.
// MODE 0: expert FFN1 (gather x rows) -> gelu (tf32-rounded) -> g_Hexp
// MODE 1: shared FFN1 (x)            -> gelu (tf32-rounded) -> g_Hs
// MODE 2: shared FFN2 (g_Hs, pre-rounded A, volatile raw loads) -> +bias -> out
// MODE 3: expert FFN2 (g_Hexp, pre-rounded A, volatile raw loads)
//         -> wt*(+bias) -> g_Y[slot]
// ---------------------------------------------------------------------------
template <int MODE, int KDIM, int NDIM>
__global__ __launch_bounds__(256, 1)
void mma_gemm(const float* __restrict__ Ain,
              const float* __restrict__ Bmat_in,
              const float* __restrict__ bias,
              float* __restrict__ outp) {
    using namespace cfg;
    extern __shared__ char smem[];
    const int t = threadIdx.x, wid = t >> 5, lid = t & 31;
    const int g = lid >> 2, tg = lid & 3;
    const int e = blockIdx.z, m0 = blockIdx.x * BM, n0 = blockIdx.y * BN;

    if (MODE == 0 || MODE == 3) {
        if (m0 >= g_cnt[e]) return;
    }

    int*   s_arow = reinterpret_cast<int*>(smem);
    int*   s_oidx = reinterpret_cast<int*>(smem + 512);
    float* s_w    = reinterpret_cast<float*>(smem + 1024);
    const uint32_t sb = smem_u32(smem);

    const float* Bmat = Bmat_in + ((MODE == 0 || MODE == 3)
                                       ? (size_t)e * KDIM * NDIM : 0);
    const float* Asrc = (MODE == 2) ? g_Hs : (MODE == 3) ? g_Hexp : Ain;
    const float* bias_p = bias + ((MODE == 0 || MODE == 3) ? (size_t)e * NDIM : 0);

    if (t < BM) {
        int r = m0 + t;
        if (MODE == 0) {
            bool v = r < g_cnt[e];
            s_arow[t] = v ? g_tok[e * TOK + r] * D : -1;
            s_oidx[t] = (e * TOK + r) * H;
        } else if (MODE == 1) {
            s_arow[t] = r * D; s_oidx[t] = r * H;
        } else if (MODE == 2) {
            s_arow[t] = r * H; s_oidx[t] = r * D;
        } else {
            bool v = r < g_cnt[e];
            s_arow[t] = v ? (e * TOK + r) * H : -1;
            s_oidx[t] = v ? g_slot[e * TOK + r] * D : -1;
            s_w[t]    = v ? g_wt[e * TOK + r] : 0.f;
        }
    }
    __syncthreads();

    auto load_stage = [&](int stage, int k0) {
        uint32_t ab = sb + STAGE_OFF + stage * STAGE_BYTES;
        uint32_t bb = ab + A_BYTES;
#pragma unroll
        for (int j = 0; j < 4; j++) {               // A: 128 rows x 8 float4
            int idx = j * 256 + t, row = idx >> 3, c4 = idx & 7;
            int ro = s_arow[row];
            int sz = (ro >= 0) ? 16 : 0;
            const float* src = Asrc + (size_t)(ro < 0 ? 0 : ro) + k0 + c4 * 4;
            cp16(ab + (row * A_STRIDE + c4 * 4) * 4, src, sz);
        }
#pragma unroll
        for (int j = 0; j < 4; j++) {               // B: 32 k-rows x 32 float4
            int idx = j * 256 + t, k = idx >> 5, c4 = idx & 31;
            const float* src = Bmat + (size_t)(k0 + k) * NDIM + n0 + c4 * 4;
            cp16(bb + (k * B_STRIDE + c4 * 4) * 4, src, 16);
        }
        CP_COMMIT();
    };

    constexpr int NCH = KDIM / BK;
    const int wm = (wid & 1) * 64, wn = (wid >> 1) * 32;
    float acc[4][4][4] = {};

    load_stage(0, 0);

    for (int it = 0; it < NCH; it++) {
        if (it + 1 < NCH)
            load_stage((it + 1) & 1, (it + 1) * BK);
        else
            CP_COMMIT();                              // keep group numbering
        CP_WAIT1();
        __syncthreads();

        const uint32_t a_addr = sb + STAGE_OFF + (it & 1) * STAGE_BYTES;
        const float* As = reinterpret_cast<const float*>(
            smem + STAGE_OFF + (it & 1) * STAGE_BYTES);
        const float* Bs = As + A_BYTES / 4;

#pragma unroll
        for (int s = 0; s < BK / 8; s++) {
            uint32_t bf[4][2];
#pragma unroll
            for (int j = 0; j < 4; j++) {
                const float* bp = Bs + (s * 8 + tg) * B_STRIDE + wn + j * 8 + g;
                bf[j][0] = f2tf(bp[0]);
                bf[j][1] = f2tf(bp[4 * B_STRIDE]);
            }
            if (MODE >= 2) {
                // A pre-rounded by FFN1 epilogue: raw volatile loads, per-i.
                // Volatile ordering pins the schedule -> 4 live af regs.
#pragma unroll
                for (int i = 0; i < 4; i++) {
                    uint32_t ar = a_addr +
                        ((wm + i * 16 + g) * A_STRIDE + s * 8 + tg) * 4;
                    uint32_t af[4];
                    af[0] = lds32v(ar);
                    af[1] = lds32v(ar + 8 * A_STRIDE * 4);
                    af[2] = lds32v(ar + 16);
                    af[3] = lds32v(ar + 8 * A_STRIDE * 4 + 16);
#pragma unroll
                    for (int jj = 0; jj < 4; jj++)
                        mma_tf32(acc[i][jj], af, bf[jj]);
                }
            } else {
                uint32_t af[4][4];
#pragma unroll
                for (int i = 0; i < 4; i++) {
                    const float* ap =
                        As + (wm + i * 16 + g) * A_STRIDE + s * 8 + tg;
                    af[i][0] = f2tf(ap[0]);
                    af[i][1] = f2tf(ap[8 * A_STRIDE]);
                    af[i][2] = f2tf(ap[4]);
                    af[i][3] = f2tf(ap[8 * A_STRIDE + 4]);
                }
#pragma unroll
                for (int i = 0; i < 4; i++)
#pragma unroll
                    for (int jj = 0; jj < 4; jj++)
                        mma_tf32(acc[i][jj], af[i], bf[jj]);
            }
        }
        __syncthreads();
    }

    // ---- epilogue ----
    float* dst = (MODE == 0) ? g_Hexp : (MODE == 1) ? g_Hs :
                 (MODE == 2) ? outp : g_Y;
#pragma unroll
    for (int i = 0; i < 4; i++) {
        int lr0 = wm + i * 16 + g, lr1 = lr0 + 8;
        int o0 = s_oidx[lr0], o1 = s_oidx[lr1];
        float w0 = (MODE == 3) ? s_w[lr0] : 1.f;
        float w1 = (MODE == 3) ? s_w[lr1] : 1.f;
#pragma unroll
        for (int j = 0; j < 4; j++) {
            int col = n0 + wn + j * 8 + 2 * tg;
            float2 bb = *reinterpret_cast<const float2*>(bias_p + col);
            float v00 = acc[i][j][0] + bb.x, v01 = acc[i][j][1] + bb.y;
            float v10 = acc[i][j][2] + bb.x, v11 = acc[i][j][3] + bb.y;
            if (MODE <= 1) {
                // gelu, then rna-round in place (same rounding point as the
                // in-loop cvt it replaces -> bitwise-identical downstream)
                v00 = __uint_as_float(f2tf(gelu_exact(v00)));
                v01 = __uint_as_float(f2tf(gelu_exact(v01)));
                v10 = __uint_as_float(f2tf(gelu_exact(v10)));
                v11 = __uint_as_float(f2tf(gelu_exact(v11)));
            } else if (MODE == 3) {
                v00 *= w0; v01 *= w0; v10 *= w1; v11 *= w1;
            }
            if (!((MODE == 3) && o0 < 0))
                *reinterpret_cast<float2*>(dst + (size_t)o0 + col) =
                    make_float2(v00, v01);
            if (!((MODE == 3) && o1 < 0))
                *reinterpret_cast<float2*>(dst + (size_t)o1 + col) =
                    make_float2(v10, v11);
        }
    }
}

// out[t] (shared-expert result) += Y[2t] + Y[2t+1]
__global__ void combine_kernel(float* __restrict__ out) {
    using namespace cfg;
    int idx = blockIdx.x * blockDim.x + threadIdx.x;
    int tok = idx / (D / 4), c4 = idx % (D / 4);
    float4 y0 = reinterpret_cast<const float4*>(g_Y + (size_t)(2 * tok) * D)[c4];
    float4 y1 = reinterpret_cast<const float4*>(g_Y + (size_t)(2 * tok + 1) * D)[c4];
    float4* o = reinterpret_cast<float4*>(out) + idx;
    float4 v = *o;
    v.x += y0.x + y1.x; v.y += y0.y + y1.y;
    v.z += y0.z + y1.z; v.w += y0.w + y1.w;
    *o = v;
}

extern "C" void kernel_launch(void* const* d_in, const int* in_sizes, int n_in,
                              void* d_out, int out_size) {
    using namespace cfg;
    const float* x   = (const float*)d_in[0];
    const float* gW  = (const float*)d_in[1];
    const float* W1  = (const float*)d_in[2];
    const float* b1  = (const float*)d_in[3];
    const float* W2  = (const float*)d_in[4];
    const float* b2  = (const float*)d_in[5];
    const float* Ws1 = (const float*)d_in[6];
    const float* bs1 = (const float*)d_in[7];
    const float* Ws2 = (const float*)d_in[8];
    const float* bs2 = (const float*)d_in[9];
    const float* rs  = (const float*)d_in[10];
    float* out = (float*)d_out;

    cudaFuncSetAttribute(mma_gemm<0, D, H>, cudaFuncAttributeMaxDynamicSharedMemorySize, SMEM_BYTES);
    cudaFuncSetAttribute(mma_gemm<1, D, H>, cudaFuncAttributeMaxDynamicSharedMemorySize, SMEM_BYTES);
    cudaFuncSetAttribute(mma_gemm<2, H, D>, cudaFuncAttributeMaxDynamicSharedMemorySize, SMEM_BYTES);
    cudaFuncSetAttribute(mma_gemm<3, H, D>, cudaFuncAttributeMaxDynamicSharedMemorySize, SMEM_BYTES);

    zero_cnt_kernel<<<1, 32>>>();
    gate_kernel<<<TOK / 8, 256>>>(x, gW, rs);

    mma_gemm<0, D, H><<<dim3(TOK / BM, H / BN, E), 256, SMEM_BYTES>>>(x, W1, b1, nullptr);
    mma_gemm<3, H, D><<<dim3(TOK / BM, D / BN, E), 256, SMEM_BYTES>>>(nullptr, W2, b2, nullptr);
    mma_gemm<1, D, H><<<dim3(TOK / BM, H / BN, 1), 256, SMEM_BYTES>>>(x, Ws1, bs1, nullptr);
    mma_gemm<2, H, D><<<dim3(TOK / BM, D / BN, 1), 256, SMEM_BYTES>>>(nullptr, Ws2, bs2, out);
    combine_kernel<<<(TOK * D / 4) / 256, 256>>>(out);
}

// round 15
// speedup vs baseline: 1.2672x; 1.2672x over previous
#include <cuda_runtime.h>
#include <cuda_fp16.h>
#include <math.h>
#include <cstdint>

// ---------------------------------------------------------------------------
// SparseExpertRouter: B=4,S=2048,D=1024,E=8,H=512,K=2 (+shared expert)
// Round 15: FFN1 = tf32 (R13 codegen, unchanged mainloop) storing fp16
// activations; FFN2 = fp16 m16n8k16 (half the instructions, 2x K per MMA).
// No new device globals (H buffers reinterpreted as half), no converter
// kernels, no static guards.
// ---------------------------------------------------------------------------

namespace cfg {
constexpr int TOK = 8192;
constexpr int D   = 1024;
constexpr int E   = 8;
constexpr int H   = 512;
constexpr int BM  = 128, BN = 128, BK = 32;
// FFN1 (tf32) smem
constexpr int A_STRIDE = BK + 4;                  // floats
constexpr int B_STRIDE = BN + 4;                  // floats
constexpr int A_BYTES  = BM * A_STRIDE * 4;       // 18432
constexpr int B_BYTES  = BK * B_STRIDE * 4;       // 16896
constexpr int STAGE1   = A_BYTES + B_BYTES;       // 35328
constexpr int STAGE_OFF = 1536;
constexpr int SMEM1    = STAGE_OFF + 2 * STAGE1;  // 72192
// FFN2 (fp16 A) smem
constexpr int AH_STRIDE = BK + 8;                 // halves (40)
constexpr int AH_BYTES  = BM * AH_STRIDE * 2;     // 10240
constexpr int STAGE2    = AH_BYTES + B_BYTES;     // 27136
constexpr int SMEM2     = STAGE_OFF + 2 * STAGE2; // 55808
}

// ---- device scratch (same set/sizes as R13) ----
__device__ __align__(16) float g_Hexp[(size_t)cfg::E * cfg::TOK * cfg::H];
__device__ __align__(16) float g_Hs  [cfg::TOK * cfg::H];
__device__ __align__(16) float g_Y   [2 * cfg::TOK * cfg::D];
__device__ int   g_tok [cfg::E * cfg::TOK];
__device__ int   g_slot[cfg::E * cfg::TOK];
__device__ float g_wt  [cfg::E * cfg::TOK];
__device__ int   g_cnt [cfg::E];

// ---- helpers ----
__device__ __forceinline__ void cp16(uint32_t dst, const void* src, int sz) {
    asm volatile("cp.async.cg.shared.global [%0], [%1], 16, %2;\n"
                 :: "r"(dst), "l"(src), "r"(sz));
}
#define CP_COMMIT() asm volatile("cp.async.commit_group;\n" ::: "memory")
#define CP_WAIT1()  asm volatile("cp.async.wait_group 1;\n" ::: "memory")

__device__ __forceinline__ uint32_t smem_u32(const void* p) {
    uint32_t a;
    asm("{ .reg .u64 t; cvta.to.shared.u64 t, %1; cvt.u32.u64 %0, t; }"
        : "=r"(a) : "l"(p));
    return a;
}
__device__ __forceinline__ uint32_t f2tf(float f) {
    uint32_t u;
    asm("cvt.rna.tf32.f32 %0, %1;" : "=r"(u) : "f"(f));
    return u;
}
// pack_f16x2(hi, lo): d.hi = cvt(hi), d.lo = cvt(lo)
__device__ __forceinline__ uint32_t pack_f16x2(float hi, float lo) {
    uint32_t u;
    asm("cvt.rn.f16x2.f32 %0, %1, %2;" : "=r"(u) : "f"(hi), "f"(lo));
    return u;
}
__device__ __forceinline__ void mma_tf32(float* c, const uint32_t* a,
                                         const uint32_t* b) {
    asm volatile(
        "mma.sync.aligned.m16n8k8.row.col.f32.tf32.tf32.f32 "
        "{%0,%1,%2,%3},{%4,%5,%6,%7},{%8,%9},{%0,%1,%2,%3};"
        : "+f"(c[0]), "+f"(c[1]), "+f"(c[2]), "+f"(c[3])
        : "r"(a[0]), "r"(a[1]), "r"(a[2]), "r"(a[3]), "r"(b[0]), "r"(b[1]));
}
__device__ __forceinline__ void mma_f16(float* c, const uint32_t* a,
                                        const uint32_t* b) {
    asm volatile(
        "mma.sync.aligned.m16n8k16.row.col.f32.f16.f16.f32 "
        "{%0,%1,%2,%3},{%4,%5,%6,%7},{%8,%9},{%0,%1,%2,%3};"
        : "+f"(c[0]), "+f"(c[1]), "+f"(c[2]), "+f"(c[3])
        : "r"(a[0]), "r"(a[1]), "r"(a[2]), "r"(a[3]), "r"(b[0]), "r"(b[1]));
}
__device__ __forceinline__ float gelu_exact(float v) {
    return 0.5f * v * (1.0f + erff(v * 0.7071067811865476f));
}

// ---------------------------------------------------------------------------
__global__ void zero_cnt_kernel() {
    if (threadIdx.x < cfg::E) g_cnt[threadIdx.x] = 0;
}

// One warp per token: gate scores, sigmoid*scale, top-2, normalize, lists.
__global__ void gate_kernel(const float* __restrict__ x,
                            const float* __restrict__ gW,
                            const float* __restrict__ route_scale) {
    using namespace cfg;
    int warp = (blockIdx.x * blockDim.x + threadIdx.x) >> 5;
    int lane = threadIdx.x & 31;
    if (warp >= TOK) return;
    const float* xr = x + (size_t)warp * D;

    float acc[E] = {0.f, 0.f, 0.f, 0.f, 0.f, 0.f, 0.f, 0.f};
    for (int d = lane; d < D; d += 32) {
        float xv = xr[d];
        const float4* g4 = reinterpret_cast<const float4*>(gW + (size_t)d * E);
        float4 a = g4[0], b = g4[1];
        acc[0] += xv * a.x; acc[1] += xv * a.y; acc[2] += xv * a.z; acc[3] += xv * a.w;
        acc[4] += xv * b.x; acc[5] += xv * b.y; acc[6] += xv * b.z; acc[7] += xv * b.w;
    }
#pragma unroll
    for (int e = 0; e < E; e++)
#pragma unroll
        for (int o = 16; o > 0; o >>= 1)
            acc[e] += __shfl_down_sync(0xffffffffu, acc[e], o);

    if (lane == 0) {
        float scale = route_scale[0];
        float s[E];
#pragma unroll
        for (int e = 0; e < E; e++) s[e] = scale / (1.0f + expf(-acc[e]));
        int i0 = 0;
#pragma unroll
        for (int e = 1; e < E; e++) if (s[e] > s[i0]) i0 = e;
        int i1 = -1;
#pragma unroll
        for (int e = 0; e < E; e++) {
            if (e == i0) continue;
            if (i1 < 0 || s[e] > s[i1]) i1 = e;
        }
        float inv = 1.0f / (s[i0] + s[i1]);
        int p0 = atomicAdd(&g_cnt[i0], 1);
        g_tok [i0 * TOK + p0] = warp;
        g_slot[i0 * TOK + p0] = warp * 2 + 0;
        g_wt  [i0 * TOK + p0] = s[i0] * inv;
        int p1 = atomicAdd(&g_cnt[i1], 1);
        g_tok [i1 * TOK + p1] = warp;
        g_slot[i1 * TOK + p1] = warp * 2 + 1;
        g_wt  [i1 * TOK + p1] = s[i1] * inv;
    }
}

// ---------------------------------------------------------------------------
// FFN1: tf32 mma.sync (R13 mainloop), epilogue gelu -> packed fp16 store.
// GATHER=1: expert (z=e, gather list) -> (half*)g_Hexp
// GATHER=0: shared (all tokens)       -> (half*)g_Hs
// ---------------------------------------------------------------------------
template <int GATHER>
__global__ __launch_bounds__(256, 1)
void ffn1_gemm(const float* __restrict__ Ain,
               const float* __restrict__ Bmat_in,
               const float* __restrict__ bias) {
    using namespace cfg;
    constexpr int KDIM = D, NDIM = H;
    extern __shared__ char smem[];
    const int t = threadIdx.x, wid = t >> 5, lid = t & 31;
    const int g = lid >> 2, tg = lid & 3;
    const int e = blockIdx.z, m0 = blockIdx.x * BM, n0 = blockIdx.y * BN;

    if (GATHER) { if (m0 >= g_cnt[e]) return; }

    int* s_arow = reinterpret_cast<int*>(smem);
    int* s_oidx = reinterpret_cast<int*>(smem + 512);
    const uint32_t sb = smem_u32(smem);

    const float* Bmat = Bmat_in + (GATHER ? (size_t)e * KDIM * NDIM : 0);
    const float* bias_p = bias + (GATHER ? (size_t)e * NDIM : 0);

    if (t < BM) {
        int r = m0 + t;
        if (GATHER) {
            bool v = r < g_cnt[e];
            s_arow[t] = v ? g_tok[e * TOK + r] * D : -1;
            s_oidx[t] = (e * TOK + r) * H;           // pad rows hit scratch
        } else {
            s_arow[t] = r * D;
            s_oidx[t] = r * H;
        }
    }
    __syncthreads();

    auto load_stage = [&](int stage, int k0) {
        uint32_t ab = sb + STAGE_OFF + stage * STAGE1;
        uint32_t bb = ab + A_BYTES;
#pragma unroll
        for (int j = 0; j < 4; j++) {               // A: 128 rows x 8 float4
            int idx = j * 256 + t, row = idx >> 3, c4 = idx & 7;
            int ro = s_arow[row];
            int sz = (ro >= 0) ? 16 : 0;
            const float* src = Ain + (size_t)(ro < 0 ? 0 : ro) + k0 + c4 * 4;
            cp16(ab + (row * A_STRIDE + c4 * 4) * 4, src, sz);
        }
#pragma unroll
        for (int j = 0; j < 4; j++) {               // B: 32 k-rows x 32 float4
            int idx = j * 256 + t, k = idx >> 5, c4 = idx & 31;
            const float* src = Bmat + (size_t)(k0 + k) * NDIM + n0 + c4 * 4;
            cp16(bb + (k * B_STRIDE + c4 * 4) * 4, src, 16);
        }
        CP_COMMIT();
    };

    constexpr int NCH = KDIM / BK;
    const int wm = (wid & 1) * 64, wn = (wid >> 1) * 32;
    float acc[4][4][4] = {};

    load_stage(0, 0);

    for (int it = 0; it < NCH; it++) {
        if (it + 1 < NCH)
            load_stage((it + 1) & 1, (it + 1) * BK);
        else
            CP_COMMIT();
        CP_WAIT1();
        __syncthreads();

        const float* As = reinterpret_cast<const float*>(
            smem + STAGE_OFF + (it & 1) * STAGE1);
        const float* Bs = As + A_BYTES / 4;

#pragma unroll
        for (int s = 0; s < BK / 8; s++) {
            uint32_t af[4][4], bf[4][2];
#pragma unroll
            for (int i = 0; i < 4; i++) {
                const float* ap = As + (wm + i * 16 + g) * A_STRIDE + s * 8 + tg;
                af[i][0] = f2tf(ap[0]);
                af[i][1] = f2tf(ap[8 * A_STRIDE]);
                af[i][2] = f2tf(ap[4]);
                af[i][3] = f2tf(ap[8 * A_STRIDE + 4]);
            }
#pragma unroll
            for (int j = 0; j < 4; j++) {
                const float* bp = Bs + (s * 8 + tg) * B_STRIDE + wn + j * 8 + g;
                bf[j][0] = f2tf(bp[0]);
                bf[j][1] = f2tf(bp[4 * B_STRIDE]);
            }
#pragma unroll
            for (int i = 0; i < 4; i++)
#pragma unroll
                for (int jj = 0; jj < 4; jj++)
                    mma_tf32(acc[i][jj], af[i], bf[jj]);
        }
        __syncthreads();
    }

    // ---- epilogue: gelu -> fp16 pack -> u32 store ----
    __half* dst = reinterpret_cast<__half*>(GATHER ? g_Hexp : g_Hs);
#pragma unroll
    for (int i = 0; i < 4; i++) {
        int lr0 = wm + i * 16 + g, lr1 = lr0 + 8;
        int o0 = s_oidx[lr0], o1 = s_oidx[lr1];
#pragma unroll
        for (int j = 0; j < 4; j++) {
            int col = n0 + wn + j * 8 + 2 * tg;
            float2 bb = *reinterpret_cast<const float2*>(bias_p + col);
            float v00 = gelu_exact(acc[i][j][0] + bb.x);
            float v01 = gelu_exact(acc[i][j][1] + bb.y);
            float v10 = gelu_exact(acc[i][j][2] + bb.x);
            float v11 = gelu_exact(acc[i][j][3] + bb.y);
            *reinterpret_cast<uint32_t*>(dst + (size_t)o0 + col) =
                pack_f16x2(v01, v00);
            *reinterpret_cast<uint32_t*>(dst + (size_t)o1 + col) =
                pack_f16x2(v11, v10);
        }
    }
}

// ---------------------------------------------------------------------------
// FFN2: fp16 m16n8k16. A = fp16 activations (g_Hexp/g_Hs as half), B = fp32
// weights converted in-loop via cvt.rn.f16x2.f32. fp32 accumulate.
// EXPERT=1: rows (e*TOK+r)*H, W2[e], b2[e], wt*(v+b) -> g_Y[slot]
// EXPERT=0: rows r*H, Ws2, bs2, (v+b) -> outp
// ---------------------------------------------------------------------------
template <int EXPERT>
__global__ __launch_bounds__(256, 1)
void ffn2_gemm(const float* __restrict__ Bmat_in,
               const float* __restrict__ bias,
               float* __restrict__ outp) {
    using namespace cfg;
    constexpr int KDIM = H, NDIM = D;
    extern __shared__ char smem[];
    const int t = threadIdx.x, wid = t >> 5, lid = t & 31;
    const int g = lid >> 2, tg = lid & 3;
    const int e = blockIdx.z, m0 = blockIdx.x * BM, n0 = blockIdx.y * BN;

    if (EXPERT) { if (m0 >= g_cnt[e]) return; }

    int*   s_arow = reinterpret_cast<int*>(smem);
    int*   s_oidx = reinterpret_cast<int*>(smem + 512);
    float* s_w    = reinterpret_cast<float*>(smem + 1024);
    const uint32_t sb = smem_u32(smem);

    const __half* Ah = reinterpret_cast<const __half*>(EXPERT ? g_Hexp : g_Hs);
    const float* Bmat = Bmat_in + (EXPERT ? (size_t)e * KDIM * NDIM : 0);
    const float* bias_p = bias + (EXPERT ? (size_t)e * NDIM : 0);

    if (t < BM) {
        int r = m0 + t;
        if (EXPERT) {
            bool v = r < g_cnt[e];
            s_arow[t] = v ? (e * TOK + r) * H : -1;
            s_oidx[t] = v ? g_slot[e * TOK + r] * D : -1;
            s_w[t]    = v ? g_wt[e * TOK + r] : 0.f;
        } else {
            s_arow[t] = r * H;
            s_oidx[t] = r * D;
        }
    }
    __syncthreads();

    auto load_stage = [&](int stage, int k0) {
        uint32_t ab = sb + STAGE_OFF + stage * STAGE2;
        uint32_t bb = ab + AH_BYTES;
#pragma unroll
        for (int j = 0; j < 2; j++) {               // A: 128 rows x 4 x 8 halves
            int idx = j * 256 + t, row = idx >> 2, c8 = idx & 3;
            int ro = s_arow[row];
            int sz = (ro >= 0) ? 16 : 0;
            const __half* src = Ah + (size_t)(ro < 0 ? 0 : ro) + k0 + c8 * 8;
            cp16(ab + (row * AH_STRIDE + c8 * 8) * 2, src, sz);
        }
#pragma unroll
        for (int j = 0; j < 4; j++) {               // B: 32 k-rows x 32 float4
            int idx = j * 256 + t, k = idx >> 5, c4 = idx & 31;
            const float* src = Bmat + (size_t)(k0 + k) * NDIM + n0 + c4 * 4;
            cp16(bb + (k * B_STRIDE + c4 * 4) * 4, src, 16);
        }
        CP_COMMIT();
    };

    constexpr int NCH = KDIM / BK;                  // 16
    const int wm = (wid & 1) * 64, wn = (wid >> 1) * 32;
    float acc[4][4][4] = {};

    load_stage(0, 0);

    for (int it = 0; it < NCH; it++) {
        if (it + 1 < NCH)
            load_stage((it + 1) & 1, (it + 1) * BK);
        else
            CP_COMMIT();
        CP_WAIT1();
        __syncthreads();

        const uint32_t* Ah32 = reinterpret_cast<const uint32_t*>(
            smem + STAGE_OFF + (it & 1) * STAGE2);
        const float* Bs = reinterpret_cast<const float*>(
            smem + STAGE_OFF + (it & 1) * STAGE2 + AH_BYTES);

#pragma unroll
        for (int s = 0; s < 2; s++) {               // two K=16 steps
            uint32_t bf[4][2];
#pragma unroll
            for (int j = 0; j < 4; j++) {
                const float* bp = Bs + (s * 16 + 2 * tg) * B_STRIDE
                                  + wn + j * 8 + g;
                bf[j][0] = pack_f16x2(bp[B_STRIDE], bp[0]);          // k+1|k
                bf[j][1] = pack_f16x2(bp[9 * B_STRIDE], bp[8 * B_STRIDE]);
            }
#pragma unroll
            for (int i = 0; i < 4; i++) {
                // u32 index: (row*AH_STRIDE + s*16 + 2tg)/2 halves
                const uint32_t* ap = Ah32
                    + (wm + i * 16 + g) * (AH_STRIDE / 2) + s * 8 + tg;
                uint32_t af[4];
                af[0] = ap[0];
                af[1] = ap[8 * (AH_STRIDE / 2)];
                af[2] = ap[4];
                af[3] = ap[8 * (AH_STRIDE / 2) + 4];
#pragma unroll
                for (int jj = 0; jj < 4; jj++)
                    mma_f16(acc[i][jj], af, bf[jj]);
            }
        }
        __syncthreads();
    }

    // ---- epilogue (fp32 outputs) ----
    float* dst = EXPERT ? g_Y : outp;
#pragma unroll
    for (int i = 0; i < 4; i++) {
        int lr0 = wm + i * 16 + g, lr1 = lr0 + 8;
        int o0 = s_oidx[lr0], o1 = s_oidx[lr1];
        float w0 = EXPERT ? s_w[lr0] : 1.f;
        float w1 = EXPERT ? s_w[lr1] : 1.f;
#pragma unroll
        for (int j = 0; j < 4; j++) {
            int col = n0 + wn + j * 8 + 2 * tg;
            float2 bb = *reinterpret_cast<const float2*>(bias_p + col);
            float v00 = acc[i][j][0] + bb.x, v01 = acc[i][j][1] + bb.y;
            float v10 = acc[i][j][2] + bb.x, v11 = acc[i][j][3] + bb.y;
            if (EXPERT) {
                v00 *= w0; v01 *= w0; v10 *= w1; v11 *= w1;
            }
            if (!(EXPERT && o0 < 0))
                *reinterpret_cast<float2*>(dst + (size_t)o0 + col) =
                    make_float2(v00, v01);
            if (!(EXPERT && o1 < 0))
                *reinterpret_cast<float2*>(dst + (size_t)o1 + col) =
                    make_float2(v10, v11);
        }
    }
}

// out[t] (shared-expert result) += Y[2t] + Y[2t+1]
__global__ void combine_kernel(float* __restrict__ out) {
    using namespace cfg;
    int idx = blockIdx.x * blockDim.x + threadIdx.x;
    int tok = idx / (D / 4), c4 = idx % (D / 4);
    float4 y0 = reinterpret_cast<const float4*>(g_Y + (size_t)(2 * tok) * D)[c4];
    float4 y1 = reinterpret_cast<const float4*>(g_Y + (size_t)(2 * tok + 1) * D)[c4];
    float4* o = reinterpret_cast<float4*>(out) + idx;
    float4 v = *o;
    v.x += y0.x + y1.x; v.y += y0.y + y1.y;
    v.z += y0.z + y1.z; v.w += y0.w + y1.w;
    *o = v;
}

extern "C" void kernel_launch(void* const* d_in, const int* in_sizes, int n_in,
                              void* d_out, int out_size) {
    using namespace cfg;
    const float* x   = (const float*)d_in[0];
    const float* gW  = (const float*)d_in[1];
    const float* W1  = (const float*)d_in[2];
    const float* b1  = (const float*)d_in[3];
    const float* W2  = (const float*)d_in[4];
    const float* b2  = (const float*)d_in[5];
    const float* Ws1 = (const float*)d_in[6];
    const float* bs1 = (const float*)d_in[7];
    const float* Ws2 = (const float*)d_in[8];
    const float* bs2 = (const float*)d_in[9];
    const float* rs  = (const float*)d_in[10];
    float* out = (float*)d_out;

    cudaFuncSetAttribute(ffn1_gemm<1>, cudaFuncAttributeMaxDynamicSharedMemorySize, SMEM1);
    cudaFuncSetAttribute(ffn1_gemm<0>, cudaFuncAttributeMaxDynamicSharedMemorySize, SMEM1);
    cudaFuncSetAttribute(ffn2_gemm<1>, cudaFuncAttributeMaxDynamicSharedMemorySize, SMEM2);
    cudaFuncSetAttribute(ffn2_gemm<0>, cudaFuncAttributeMaxDynamicSharedMemorySize, SMEM2);

    zero_cnt_kernel<<<1, 32>>>();
    gate_kernel<<<TOK / 8, 256>>>(x, gW, rs);

    ffn1_gemm<1><<<dim3(TOK / BM, H / BN, E), 256, SMEM1>>>(x, W1, b1);
    ffn1_gemm<0><<<dim3(TOK / BM, H / BN, 1), 256, SMEM1>>>(x, Ws1, bs1);
    ffn2_gemm<1><<<dim3(TOK / BM, D / BN, E), 256, SMEM2>>>(W2, b2, nullptr);
    ffn2_gemm<0><<<dim3(TOK / BM, D / BN, 1), 256, SMEM2>>>(Ws2, bs2, out);
    combine_kernel<<<(TOK * D / 4) / 256, 256>>>(out);
}

// round 16
// speedup vs baseline: 1.4825x; 1.1699x over previous
#include <cuda_runtime.h>
#include <cuda_fp16.h>
#include <math.h>
#include <cstdint>

// ---------------------------------------------------------------------------
// SparseExpertRouter: B=4,S=2048,D=1024,E=8,H=512,K=2 (+shared expert)
// Round 16: all four GEMMs fp16 m16n8k16 (fp32 accumulate). gate_kernel emits
// xh = fp16(x) into the head of g_Y (dead until FFN2-expert overwrites it).
// No new device globals, no converter kernels, no static guards.
// ---------------------------------------------------------------------------

namespace cfg {
constexpr int TOK = 8192;
constexpr int D   = 1024;
constexpr int E   = 8;
constexpr int H   = 512;
constexpr int BM  = 128, BN = 128, BK = 32;
constexpr int B_STRIDE  = BN + 4;                 // floats (132)
constexpr int B_BYTES   = BK * B_STRIDE * 4;      // 16896
constexpr int AH_STRIDE = BK + 8;                 // halves (40)
constexpr int AH_BYTES  = BM * AH_STRIDE * 2;     // 10240
constexpr int STAGE     = AH_BYTES + B_BYTES;     // 27136
constexpr int STAGE_OFF = 1536;
constexpr int SMEM_BYTES = STAGE_OFF + 2 * STAGE; // 55808
}

// ---- device scratch (same set/sizes as R13/R15) ----
__device__ __align__(16) float g_Hexp[(size_t)cfg::E * cfg::TOK * cfg::H];
__device__ __align__(16) float g_Hs  [cfg::TOK * cfg::H];
__device__ __align__(16) float g_Y   [2 * cfg::TOK * cfg::D];  // head doubles as xh (fp16)
__device__ int   g_tok [cfg::E * cfg::TOK];
__device__ int   g_slot[cfg::E * cfg::TOK];
__device__ float g_wt  [cfg::E * cfg::TOK];
__device__ int   g_cnt [cfg::E];

// ---- helpers ----
__device__ __forceinline__ void cp16(uint32_t dst, const void* src, int sz) {
    asm volatile("cp.async.cg.shared.global [%0], [%1], 16, %2;\n"
                 :: "r"(dst), "l"(src), "r"(sz));
}
#define CP_COMMIT() asm volatile("cp.async.commit_group;\n" ::: "memory")
#define CP_WAIT1()  asm volatile("cp.async.wait_group 1;\n" ::: "memory")

__device__ __forceinline__ uint32_t smem_u32(const void* p) {
    uint32_t a;
    asm("{ .reg .u64 t; cvta.to.shared.u64 t, %1; cvt.u32.u64 %0, t; }"
        : "=r"(a) : "l"(p));
    return a;
}
// pack_f16x2(hi, lo): d.hi = cvt(hi), d.lo = cvt(lo)
__device__ __forceinline__ uint32_t pack_f16x2(float hi, float lo) {
    uint32_t u;
    asm("cvt.rn.f16x2.f32 %0, %1, %2;" : "=r"(u) : "f"(hi), "f"(lo));
    return u;
}
__device__ __forceinline__ void mma_f16(float* c, const uint32_t* a,
                                        const uint32_t* b) {
    asm volatile(
        "mma.sync.aligned.m16n8k16.row.col.f32.f16.f16.f32 "
        "{%0,%1,%2,%3},{%4,%5,%6,%7},{%8,%9},{%0,%1,%2,%3};"
        : "+f"(c[0]), "+f"(c[1]), "+f"(c[2]), "+f"(c[3])
        : "r"(a[0]), "r"(a[1]), "r"(a[2]), "r"(a[3]), "r"(b[0]), "r"(b[1]));
}
__device__ __forceinline__ float gelu_exact(float v) {
    return 0.5f * v * (1.0f + erff(v * 0.7071067811865476f));
}

// ---------------------------------------------------------------------------
__global__ void zero_cnt_kernel() {
    if (threadIdx.x < cfg::E) g_cnt[threadIdx.x] = 0;
}

// One warp per token: gate scores (fp32 x), top-2, normalize, lists.
// Side output: xh = fp16(x) into the head of g_Y (consumed by FFN1).
__global__ void gate_kernel(const float* __restrict__ x,
                            const float* __restrict__ gW,
                            const float* __restrict__ route_scale) {
    using namespace cfg;
    int warp = (blockIdx.x * blockDim.x + threadIdx.x) >> 5;
    int lane = threadIdx.x & 31;
    if (warp >= TOK) return;
    const float* xr = x + (size_t)warp * D;
    __half* xh = reinterpret_cast<__half*>(g_Y) + (size_t)warp * D;

    float acc[E] = {0.f, 0.f, 0.f, 0.f, 0.f, 0.f, 0.f, 0.f};
    for (int d = lane; d < D; d += 32) {
        float xv = xr[d];
        xh[d] = __float2half_rn(xv);
        const float4* g4 = reinterpret_cast<const float4*>(gW + (size_t)d * E);
        float4 a = g4[0], b = g4[1];
        acc[0] += xv * a.x; acc[1] += xv * a.y; acc[2] += xv * a.z; acc[3] += xv * a.w;
        acc[4] += xv * b.x; acc[5] += xv * b.y; acc[6] += xv * b.z; acc[7] += xv * b.w;
    }
#pragma unroll
    for (int e = 0; e < E; e++)
#pragma unroll
        for (int o = 16; o > 0; o >>= 1)
            acc[e] += __shfl_down_sync(0xffffffffu, acc[e], o);

    if (lane == 0) {
        float scale = route_scale[0];
        float s[E];
#pragma unroll
        for (int e = 0; e < E; e++) s[e] = scale / (1.0f + expf(-acc[e]));
        int i0 = 0;
#pragma unroll
        for (int e = 1; e < E; e++) if (s[e] > s[i0]) i0 = e;
        int i1 = -1;
#pragma unroll
        for (int e = 0; e < E; e++) {
            if (e == i0) continue;
            if (i1 < 0 || s[e] > s[i1]) i1 = e;
        }
        float inv = 1.0f / (s[i0] + s[i1]);
        int p0 = atomicAdd(&g_cnt[i0], 1);
        g_tok [i0 * TOK + p0] = warp;
        g_slot[i0 * TOK + p0] = warp * 2 + 0;
        g_wt  [i0 * TOK + p0] = s[i0] * inv;
        int p1 = atomicAdd(&g_cnt[i1], 1);
        g_tok [i1 * TOK + p1] = warp;
        g_slot[i1 * TOK + p1] = warp * 2 + 1;
        g_wt  [i1 * TOK + p1] = s[i1] * inv;
    }
}

// ---------------------------------------------------------------------------
// fp16 m16n8k16 grouped GEMM, 128x128 tile, 8 warps (2m x 4n), fp32 accum.
// A fp16 in smem (cp.async from fp16 buffers); B fp32 weights packed in-loop.
// MODE 0: expert FFN1 (gather xh)  K=D,N=H -> gelu -> (half*)g_Hexp
// MODE 1: shared FFN1 (xh)         K=D,N=H -> gelu -> (half*)g_Hs
// MODE 2: shared FFN2 (g_Hs half)  K=H,N=D -> +bias -> out (float)
// MODE 3: expert FFN2 (g_Hexp half)K=H,N=D -> wt*(+bias) -> g_Y[slot] (float)
// ---------------------------------------------------------------------------
template <int MODE>
__global__ __launch_bounds__(256, 1)
void mma_gemm(const float* __restrict__ Bmat_in,
              const float* __restrict__ bias,
              float* __restrict__ outp) {
    using namespace cfg;
    constexpr int KDIM = (MODE <= 1) ? D : H;
    constexpr int NDIM = (MODE <= 1) ? H : D;
    extern __shared__ char smem[];
    const int t = threadIdx.x, wid = t >> 5, lid = t & 31;
    const int g = lid >> 2, tg = lid & 3;
    const int e = blockIdx.z, m0 = blockIdx.x * BM, n0 = blockIdx.y * BN;

    if (MODE == 0 || MODE == 3) {
        if (m0 >= g_cnt[e]) return;
    }

    int*   s_arow = reinterpret_cast<int*>(smem);
    int*   s_oidx = reinterpret_cast<int*>(smem + 512);
    float* s_w    = reinterpret_cast<float*>(smem + 1024);
    const uint32_t sb = smem_u32(smem);

    const __half* Ah =
        (MODE <= 1) ? reinterpret_cast<const __half*>(g_Y) :
        (MODE == 2) ? reinterpret_cast<const __half*>(g_Hs)
                    : reinterpret_cast<const __half*>(g_Hexp);
    const float* Bmat = Bmat_in + ((MODE == 0 || MODE == 3)
                                       ? (size_t)e * KDIM * NDIM : 0);
    const float* bias_p = bias + ((MODE == 0 || MODE == 3) ? (size_t)e * NDIM : 0);

    if (t < BM) {
        int r = m0 + t;
        if (MODE == 0) {
            bool v = r < g_cnt[e];
            s_arow[t] = v ? g_tok[e * TOK + r] * D : -1;
            s_oidx[t] = (e * TOK + r) * H;           // pad rows hit scratch
        } else if (MODE == 1) {
            s_arow[t] = r * D; s_oidx[t] = r * H;
        } else if (MODE == 2) {
            s_arow[t] = r * H; s_oidx[t] = r * D;
        } else {
            bool v = r < g_cnt[e];
            s_arow[t] = v ? (e * TOK + r) * H : -1;
            s_oidx[t] = v ? g_slot[e * TOK + r] * D : -1;
            s_w[t]    = v ? g_wt[e * TOK + r] : 0.f;
        }
    }
    __syncthreads();

    auto load_stage = [&](int stage, int k0) {
        uint32_t ab = sb + STAGE_OFF + stage * STAGE;
        uint32_t bb = ab + AH_BYTES;
#pragma unroll
        for (int j = 0; j < 2; j++) {               // A: 128 rows x 4 x 8 halves
            int idx = j * 256 + t, row = idx >> 2, c8 = idx & 3;
            int ro = s_arow[row];
            int sz = (ro >= 0) ? 16 : 0;
            const __half* src = Ah + (size_t)(ro < 0 ? 0 : ro) + k0 + c8 * 8;
            cp16(ab + (row * AH_STRIDE + c8 * 8) * 2, src, sz);
        }
#pragma unroll
        for (int j = 0; j < 4; j++) {               // B: 32 k-rows x 32 float4
            int idx = j * 256 + t, k = idx >> 5, c4 = idx & 31;
            const float* src = Bmat + (size_t)(k0 + k) * NDIM + n0 + c4 * 4;
            cp16(bb + (k * B_STRIDE + c4 * 4) * 4, src, 16);
        }
        CP_COMMIT();
    };

    constexpr int NCH = KDIM / BK;
    const int wm = (wid & 1) * 64, wn = (wid >> 1) * 32;
    float acc[4][4][4] = {};

    load_stage(0, 0);

    for (int it = 0; it < NCH; it++) {
        if (it + 1 < NCH)
            load_stage((it + 1) & 1, (it + 1) * BK);
        else
            CP_COMMIT();
        CP_WAIT1();
        __syncthreads();

        const uint32_t* Ah32 = reinterpret_cast<const uint32_t*>(
            smem + STAGE_OFF + (it & 1) * STAGE);
        const float* Bs = reinterpret_cast<const float*>(
            smem + STAGE_OFF + (it & 1) * STAGE + AH_BYTES);

#pragma unroll
        for (int s = 0; s < 2; s++) {               // two K=16 steps
            uint32_t bf[4][2];
#pragma unroll
            for (int j = 0; j < 4; j++) {
                const float* bp = Bs + (s * 16 + 2 * tg) * B_STRIDE
                                  + wn + j * 8 + g;
                bf[j][0] = pack_f16x2(bp[B_STRIDE], bp[0]);          // k+1|k
                bf[j][1] = pack_f16x2(bp[9 * B_STRIDE], bp[8 * B_STRIDE]);
            }
#pragma unroll
            for (int i = 0; i < 4; i++) {
                const uint32_t* ap = Ah32
                    + (wm + i * 16 + g) * (AH_STRIDE / 2) + s * 8 + tg;
                uint32_t af[4];
                af[0] = ap[0];
                af[1] = ap[8 * (AH_STRIDE / 2)];
                af[2] = ap[4];
                af[3] = ap[8 * (AH_STRIDE / 2) + 4];
#pragma unroll
                for (int jj = 0; jj < 4; jj++)
                    mma_f16(acc[i][jj], af, bf[jj]);
            }
        }
        __syncthreads();
    }

    // ---- epilogue ----
#pragma unroll
    for (int i = 0; i < 4; i++) {
        int lr0 = wm + i * 16 + g, lr1 = lr0 + 8;
        int o0 = s_oidx[lr0], o1 = s_oidx[lr1];
        float w0 = (MODE == 3) ? s_w[lr0] : 1.f;
        float w1 = (MODE == 3) ? s_w[lr1] : 1.f;
#pragma unroll
        for (int j = 0; j < 4; j++) {
            int col = n0 + wn + j * 8 + 2 * tg;
            float2 bb = *reinterpret_cast<const float2*>(bias_p + col);
            float v00 = acc[i][j][0] + bb.x, v01 = acc[i][j][1] + bb.y;
            float v10 = acc[i][j][2] + bb.x, v11 = acc[i][j][3] + bb.y;
            if (MODE <= 1) {
                __half* dst = reinterpret_cast<__half*>(
                    (MODE == 0) ? g_Hexp : g_Hs);
                v00 = gelu_exact(v00); v01 = gelu_exact(v01);
                v10 = gelu_exact(v10); v11 = gelu_exact(v11);
                *reinterpret_cast<uint32_t*>(dst + (size_t)o0 + col) =
                    pack_f16x2(v01, v00);
                *reinterpret_cast<uint32_t*>(dst + (size_t)o1 + col) =
                    pack_f16x2(v11, v10);
            } else {
                float* dst = (MODE == 2) ? outp : g_Y;
                if (MODE == 3) {
                    v00 *= w0; v01 *= w0; v10 *= w1; v11 *= w1;
                }
                if (!((MODE == 3) && o0 < 0))
                    *reinterpret_cast<float2*>(dst + (size_t)o0 + col) =
                        make_float2(v00, v01);
                if (!((MODE == 3) && o1 < 0))
                    *reinterpret_cast<float2*>(dst + (size_t)o1 + col) =
                        make_float2(v10, v11);
            }
        }
    }
}

// out[t] (shared-expert result) += Y[2t] + Y[2t+1]
__global__ void combine_kernel(float* __restrict__ out) {
    using namespace cfg;
    int idx = blockIdx.x * blockDim.x + threadIdx.x;
    int tok = idx / (D / 4), c4 = idx % (D / 4);
    float4 y0 = reinterpret_cast<const float4*>(g_Y + (size_t)(2 * tok) * D)[c4];
    float4 y1 = reinterpret_cast<const float4*>(g_Y + (size_t)(2 * tok + 1) * D)[c4];
    float4* o = reinterpret_cast<float4*>(out) + idx;
    float4 v = *o;
    v.x += y0.x + y1.x; v.y += y0.y + y1.y;
    v.z += y0.z + y1.z; v.w += y0.w + y1.w;
    *o = v;
}

extern "C" void kernel_launch(void* const* d_in, const int* in_sizes, int n_in,
                              void* d_out, int out_size) {
    using namespace cfg;
    const float* x   = (const float*)d_in[0];
    const float* gW  = (const float*)d_in[1];
    const float* W1  = (const float*)d_in[2];
    const float* b1  = (const float*)d_in[3];
    const float* W2  = (const float*)d_in[4];
    const float* b2  = (const float*)d_in[5];
    const float* Ws1 = (const float*)d_in[6];
    const float* bs1 = (const float*)d_in[7];
    const float* Ws2 = (const float*)d_in[8];
    const float* bs2 = (const float*)d_in[9];
    const float* rs  = (const float*)d_in[10];
    float* out = (float*)d_out;

    cudaFuncSetAttribute(mma_gemm<0>, cudaFuncAttributeMaxDynamicSharedMemorySize, SMEM_BYTES);
    cudaFuncSetAttribute(mma_gemm<1>, cudaFuncAttributeMaxDynamicSharedMemorySize, SMEM_BYTES);
    cudaFuncSetAttribute(mma_gemm<2>, cudaFuncAttributeMaxDynamicSharedMemorySize, SMEM_BYTES);
    cudaFuncSetAttribute(mma_gemm<3>, cudaFuncAttributeMaxDynamicSharedMemorySize, SMEM_BYTES);

    zero_cnt_kernel<<<1, 32>>>();
    gate_kernel<<<TOK / 8, 256>>>(x, gW, rs);      // also emits xh into g_Y

    // FFN1 reads xh (head of g_Y); FFN2-expert overwrites g_Y afterwards.
    mma_gemm<0><<<dim3(TOK / BM, H / BN, E), 256, SMEM_BYTES>>>(W1, b1, nullptr);
    mma_gemm<1><<<dim3(TOK / BM, H / BN, 1), 256, SMEM_BYTES>>>(Ws1, bs1, nullptr);
    mma_gemm<3><<<dim3(TOK / BM, D / BN, E), 256, SMEM_BYTES>>>(W2, b2, nullptr);
    mma_gemm<2><<<dim3(TOK / BM, D / BN, 1), 256, SMEM_BYTES>>>(Ws2, bs2, out);
    combine_kernel<<<(TOK * D / 4) / 256, 256>>>(out);
}